// round 16
// baseline (speedup 1.0000x reference)
#include <cuda_runtime.h>
#include <cuda_fp16.h>
#include <cstdint>
#include <math.h>

// ---------------------------------------------------------------------------
// ViT transformer block. fp16 single-pass mma.sync (fp32 accumulate).
// Dense GEMMs: BK=64, 3-stage cp.async ring, 2 CTAs/SM.
//   N=1536/2048 GEMMs: BN=128 tiles. N=512 GEMMs: BN=64 tiles (wave quant fix).
// Flash attention: 128-thread CTAs, Q resident, K/V 3-stage ring, 4 CTAs/SM.
// Prep (weight transpose/cast + LN0/LN1) fused into one launch.
// ---------------------------------------------------------------------------

#define ROWS   16384
#define DIM    512
#define INNER  512
#define QKVW   1536
#define HIDDEN 2048
#define NSEQ   1024
#define NZ     128
#define SCALE  0.125f
#define EPS    1e-5f

typedef __half fp16;

// ------------------------- device scratch ---------------------------------
__device__ __align__(256) float g_xn  [(size_t)ROWS * DIM];
__device__ __align__(256) fp16  g_hh  [(size_t)ROWS * DIM];
__device__ __align__(256) fp16  g_qkvh[(size_t)ROWS * QKVW];
__device__ __align__(256) fp16  g_aoh [(size_t)ROWS * DIM];
__device__ __align__(256) float g_x2  [(size_t)ROWS * DIM];
__device__ __align__(256) fp16  g_x2h [(size_t)ROWS * DIM];
__device__ __align__(256) fp16  g_midh[(size_t)ROWS * HIDDEN];
// transposed weights [N, K], fp16
__device__ __align__(256) fp16  g_wqkvt[(size_t)QKVW * DIM];
__device__ __align__(256) fp16  g_wot  [(size_t)DIM * INNER];
__device__ __align__(256) fp16  g_w1t  [(size_t)HIDDEN * DIM];
__device__ __align__(256) fp16  g_w2t  [(size_t)DIM * HIDDEN];

// ------------------------- PTX helpers ------------------------------------
__device__ __forceinline__ uint32_t smem_u32(const void* p) {
    uint32_t a;
    asm("{ .reg .u64 t; cvta.to.shared.u64 t, %1; cvt.u32.u64 %0, t; }"
        : "=r"(a) : "l"(p));
    return a;
}
#define CP_ASYNC_16(sa, ga) \
    asm volatile("cp.async.cg.shared.global [%0], [%1], 16;" \
                 :: "r"((uint32_t)(sa)), "l"(ga) : "memory")
#define CP_COMMIT() asm volatile("cp.async.commit_group;" ::: "memory")
#define CP_WAIT0()  asm volatile("cp.async.wait_group 0;" ::: "memory")
#define CP_WAIT1()  asm volatile("cp.async.wait_group 1;" ::: "memory")

__device__ __forceinline__ void ldsm4(uint32_t* r, uint32_t addr) {
    asm volatile("ldmatrix.sync.aligned.m8n8.x4.shared.b16 {%0,%1,%2,%3}, [%4];"
        : "=r"(r[0]), "=r"(r[1]), "=r"(r[2]), "=r"(r[3]) : "r"(addr));
}
__device__ __forceinline__ void ldsm4t(uint32_t* r, uint32_t addr) {
    asm volatile("ldmatrix.sync.aligned.m8n8.x4.trans.shared.b16 {%0,%1,%2,%3}, [%4];"
        : "=r"(r[0]), "=r"(r[1]), "=r"(r[2]), "=r"(r[3]) : "r"(addr));
}
__device__ __forceinline__ void mma_fp16(float* c, const uint32_t* a, const uint32_t* b) {
    asm volatile(
        "mma.sync.aligned.m16n8k16.row.col.f32.f16.f16.f32 "
        "{%0,%1,%2,%3}, {%4,%5,%6,%7}, {%8,%9}, {%0,%1,%2,%3};"
        : "+f"(c[0]), "+f"(c[1]), "+f"(c[2]), "+f"(c[3])
        : "r"(a[0]), "r"(a[1]), "r"(a[2]), "r"(a[3]), "r"(b[0]), "r"(b[1]));
}

__device__ __forceinline__ float gelu_f(float x) {
    return 0.5f * x * (1.0f + erff(x * 0.7071067811865475f));
}
__device__ __forceinline__ uint32_t pack_h2(fp16 a, fp16 b) {
    __half2 t = __halves2half2(a, b);
    return *(uint32_t*)&t;
}

// swizzled smem addr for a 128B-row tile (rows x 64 fp16)
__device__ __forceinline__ uint32_t sw128(uint32_t base, int row, int chunk) {
    return base + row * 128 + ((chunk ^ (row & 7)) << 4);
}

// ---------------------------------------------------------------------------
// Single-pass fp16 GEMM: C[M,N] = A[M,K] @ Bt[N,K]^T
// BM=128, BN template (128 or 64), BK=64, 3-stage ring, 2 CTAs/SM.
// 8 warps. BN=128: 2x4 warp grid, tile 64x32. BN=64: 4x2 grid, tile 32x32.
// ---------------------------------------------------------------------------
template <int EPI, int BN>
__global__ void __launch_bounds__(256, 2) mma_gemm(
    const fp16* __restrict__ Ahi, const fp16* __restrict__ Bhi,
    int M, int N, int K, int lda, int ldb,
    const float* __restrict__ bias, const float* __restrict__ res,
    float* __restrict__ Cf, fp16* __restrict__ Chi)
{
    constexpr int STAGE = (128 + BN) * 128;     // bytes per stage
    constexpr int TM = (BN == 128) ? 4 : 2;     // 16-row tiles per warp
    constexpr int WX = BN / 32;                 // warps along N
    constexpr int CH_A = 128 * 8;               // 16B chunks in A tile
    constexpr int CH_TOT = CH_A + BN * 8;

    extern __shared__ char smem[];
    uint32_t sb = smem_u32(smem);
    int tid = threadIdx.x, wid = tid >> 5, lane = tid & 31;
    int row0 = blockIdx.y * 128, col0 = blockIdx.x * BN;

    const int NC = K >> 6;

    auto load_stage = [&](int c) {
        int s = c % 3;
        uint32_t st = sb + s * STAGE;
        int k0 = c << 6;
        #pragma unroll
        for (int idx = 0; idx < CH_TOT; idx += 256) {
            int i = idx + tid;
            int isB = i >= CH_A;
            int i2 = isB ? i - CH_A : i;
            int r = i2 >> 3, ch = i2 & 7;
            uint32_t dst = sw128(st + isB * 16384, r, ch);
            const fp16* src = isB
                ? Bhi + (size_t)(col0 + r) * ldb + k0 + ch * 8
                : Ahi + (size_t)(row0 + r) * lda + k0 + ch * 8;
            CP_ASYNC_16(dst, src);
        }
        CP_COMMIT();
    };

    float acc[TM][4][4] = {};
    int mi = lane >> 3, lr = lane & 7;
    int wm = (wid / WX) * (TM * 16);
    int wn = (wid % WX) * 32;

    load_stage(0);
    load_stage(1);

    for (int c = 0; c < NC; c++) {
        if (c + 1 < NC) { CP_WAIT1(); }
        else            { CP_WAIT0(); }
        __syncthreads();
        if (c + 2 < NC) load_stage(c + 2);

        int s = c % 3;
        uint32_t stA = sb + s * STAGE;
        uint32_t stB = stA + 16384;
        #pragma unroll
        for (int ks = 0; ks < 4; ks++) {
            uint32_t ah[TM][4], bh[2][4];
            #pragma unroll
            for (int t = 0; t < TM; t++) {
                int row = wm + t * 16 + ((mi & 1) << 3) + lr;
                int ch  = ks * 2 + (mi >> 1);
                ldsm4(ah[t], sw128(stA, row, ch));
            }
            #pragma unroll
            for (int p = 0; p < 2; p++) {
                int row = wn + p * 16 + ((mi >> 1) << 3) + lr;
                int ch  = ks * 2 + (mi & 1);
                ldsm4(bh[p], sw128(stB, row, ch));
            }
            #pragma unroll
            for (int tm = 0; tm < TM; tm++)
                #pragma unroll
                for (int tn = 0; tn < 4; tn++)
                    mma_fp16(acc[tm][tn], ah[tm], &bh[tn >> 1][(tn & 1) * 2]);
        }
    }

    int g = lane >> 2, tc = lane & 3;
    #pragma unroll
    for (int tm = 0; tm < TM; tm++) {
        #pragma unroll
        for (int tn = 0; tn < 4; tn++) {
            int rr = row0 + wm + tm * 16 + g;
            int cc = col0 + wn + tn * 8 + tc * 2;
            #pragma unroll
            for (int half_ = 0; half_ < 2; half_++) {
                int r_ = rr + half_ * 8;
                float v0 = acc[tm][tn][half_ * 2 + 0];
                float v1 = acc[tm][tn][half_ * 2 + 1];
                size_t off = (size_t)r_ * N + cc;
                if (EPI == 2 || EPI == 4) {
                    float2 b2 = *(const float2*)(bias + cc);
                    float2 r2 = *(const float2*)(res + off);
                    v0 += b2.x + r2.x; v1 += b2.y + r2.y;
                    *(float2*)(Cf + off) = make_float2(v0, v1);
                } else if (EPI == 3) {
                    float2 b2 = *(const float2*)(bias + cc);
                    v0 = gelu_f(v0 + b2.x); v1 = gelu_f(v1 + b2.y);
                }
                if (EPI == 1 || EPI == 2 || EPI == 3) {
                    *(uint32_t*)(Chi + off) =
                        pack_h2(__float2half_rn(v0), __float2half_rn(v1));
                }
            }
        }
    }
}

#define GSMEM128 (3 * (128 + 128) * 128)
#define GSMEM64  (3 * (128 + 64) * 128)

// ---------------------------------------------------------------------------
// Fused flash attention (verified-best configuration).
// ---------------------------------------------------------------------------
#define FA_SMEM (8192 + 3 * 16384)

__global__ void __launch_bounds__(128, 4) flash_kernel(
    const fp16* __restrict__ qkvh, fp16* __restrict__ aoh)
{
    extern __shared__ char smem[];
    uint32_t sb = smem_u32(smem);
    int tid = threadIdx.x, wid = tid >> 5, lane = tid & 31;
    int mi = lane >> 3, lr = lane & 7;
    int g = lane >> 2, tc = lane & 3;
    int z = blockIdx.y;
    int b = z >> 6, h = (z >> 3) & 7, p = z & 7;
    int row0 = blockIdx.x * 64;
    size_t base = (size_t)((b * 8 + p)) * NSEQ * QKVW + h * 64;
    const fp16* Qh = qkvh + base;
    const fp16* Kh = qkvh + base + 512;
    const fp16* Vh = qkvh + base + 1024;

    uint32_t qoff = sb;
    uint32_t soff = sb + 8192;

    #pragma unroll
    for (int l = 0; l < 4; l++) {
        int idx = tid + l * 128;
        int r = idx >> 3, ch = idx & 7;
        CP_ASYNC_16(sw128(qoff, r, ch), Qh + (size_t)(row0 + r) * QKVW + ch * 8);
    }

    auto load_stage = [&](int c) {
        int s = c % 3;
        uint32_t st = soff + s * 16384;
        int kv0 = c << 6;
        #pragma unroll
        for (int l = 0; l < 8; l++) {
            int idx = tid + l * 128;
            int mat = idx >> 9, r = (idx >> 3) & 63, ch = idx & 7;
            const fp16* src = (mat == 0 ? Kh : Vh) + (size_t)(kv0 + r) * QKVW + ch * 8;
            CP_ASYNC_16(sw128(st + mat * 8192, r, ch), src);
        }
        CP_COMMIT();
    };

    load_stage(0);
    load_stage(1);

    float m_r[2] = {-1e30f, -1e30f};
    float l_r[2] = {0.f, 0.f};
    float O[8][4] = {};
    int qr0 = wid * 16;

    for (int c = 0; c < 16; c++) {
        if (c + 1 < 16) { CP_WAIT1(); }
        else            { CP_WAIT0(); }
        __syncthreads();
        if (c + 2 < 16) load_stage(c + 2);

        int s = c % 3;
        uint32_t kh_o = soff + s * 16384;
        uint32_t vh_o = kh_o + 8192;

        float S[8][4] = {};
        #pragma unroll
        for (int ks = 0; ks < 4; ks++) {
            uint32_t ah[4];
            {
                int row = qr0 + ((mi & 1) << 3) + lr;
                int ch  = ks * 2 + (mi >> 1);
                ldsm4(ah, sw128(qoff, row, ch));
            }
            #pragma unroll
            for (int np = 0; np < 4; np++) {
                uint32_t bh[4];
                int row = np * 16 + ((mi >> 1) << 3) + lr;
                int ch  = ks * 2 + (mi & 1);
                ldsm4(bh, sw128(kh_o, row, ch));
                mma_fp16(S[np * 2],     ah, &bh[0]);
                mma_fp16(S[np * 2 + 1], ah, &bh[2]);
            }
        }

        #pragma unroll
        for (int hf = 0; hf < 2; hf++) {
            float mx = -1e30f;
            #pragma unroll
            for (int j = 0; j < 8; j++)
                mx = fmaxf(mx, fmaxf(S[j][hf * 2], S[j][hf * 2 + 1]));
            mx = fmaxf(mx, __shfl_xor_sync(0xffffffffu, mx, 1));
            mx = fmaxf(mx, __shfl_xor_sync(0xffffffffu, mx, 2));
            float mnew = fmaxf(m_r[hf], mx);
            float alpha = exp2f(m_r[hf] - mnew);
            m_r[hf] = mnew;
            float s_ = 0.f;
            #pragma unroll
            for (int j = 0; j < 8; j++) {
                float p0 = exp2f(S[j][hf * 2]     - mnew);
                float p1 = exp2f(S[j][hf * 2 + 1] - mnew);
                S[j][hf * 2] = p0; S[j][hf * 2 + 1] = p1;
                s_ += p0 + p1;
            }
            s_ += __shfl_xor_sync(0xffffffffu, s_, 1);
            s_ += __shfl_xor_sync(0xffffffffu, s_, 2);
            l_r[hf] = l_r[hf] * alpha + s_;
            #pragma unroll
            for (int j = 0; j < 8; j++) {
                O[j][hf * 2]     *= alpha;
                O[j][hf * 2 + 1] *= alpha;
            }
        }

        uint32_t ph[4][4];
        #pragma unroll
        for (int s2 = 0; s2 < 4; s2++) {
            #pragma unroll
            for (int q4 = 0; q4 < 4; q4++) {
                int j  = s2 * 2 + (q4 >> 1);
                int k0 = (q4 & 1) * 2;
                ph[s2][q4] = pack_h2(__float2half_rn(S[j][k0]),
                                     __float2half_rn(S[j][k0 + 1]));
            }
        }

        #pragma unroll
        for (int s2 = 0; s2 < 4; s2++) {
            #pragma unroll
            for (int dp = 0; dp < 4; dp++) {
                uint32_t vhh[4];
                int row = s2 * 16 + ((mi & 1) << 3) + lr;
                int chk = dp * 2 + (mi >> 1);
                ldsm4t(vhh, sw128(vh_o, row, chk));
                mma_fp16(O[dp * 2],     ph[s2], &vhh[0]);
                mma_fp16(O[dp * 2 + 1], ph[s2], &vhh[2]);
            }
        }
    }

    float inv0 = 1.0f / l_r[0], inv1 = 1.0f / l_r[1];
    size_t obase = (size_t)(b * 8 + h) * NSEQ;
    #pragma unroll
    for (int dp = 0; dp < 8; dp++) {
        int d = dp * 8 + tc * 2;
        #pragma unroll
        for (int hf = 0; hf < 2; hf++) {
            float inv = hf ? inv1 : inv0;
            int n = row0 + qr0 + g + hf * 8;
            float v0 = O[dp][hf * 2]     * inv;
            float v1 = O[dp][hf * 2 + 1] * inv;
            size_t off = (obase + n) * DIM + p * 64 + d;
            *(uint32_t*)(aoh + off) =
                pack_h2(__float2half_rn(v0), __float2half_rn(v1));
        }
    }
}

// ---------------------------------------------------------------------------
// Fused prep: weight transpose/cast + LN0/LN1.
// ---------------------------------------------------------------------------
#define TC_BLOCKS 12288

__device__ __forceinline__ float block_sum(float v, float* sm) {
    #pragma unroll
    for (int o = 16; o > 0; o >>= 1) v += __shfl_down_sync(0xffffffffu, v, o);
    int lane = threadIdx.x & 31, wid = threadIdx.x >> 5;
    if (lane == 0) sm[wid] = v;
    __syncthreads();
    v = (threadIdx.x < 8) ? sm[threadIdx.x] : 0.0f;
    if (wid == 0) {
        #pragma unroll
        for (int o = 4; o > 0; o >>= 1) v += __shfl_down_sync(0xffffffffu, v, o);
        if (lane == 0) sm[0] = v;
    }
    __syncthreads();
    float r = sm[0];
    __syncthreads();
    return r;
}

__global__ void __launch_bounds__(256) prep_kernel(
    const float* __restrict__ Wq, fp16* __restrict__ Tq,
    const float* __restrict__ Wo, fp16* __restrict__ To,
    const float* __restrict__ W1, fp16* __restrict__ T1,
    const float* __restrict__ W2, fp16* __restrict__ T2,
    const float* __restrict__ x,
    const float* __restrict__ w0, const float* __restrict__ b0,
    const float* __restrict__ w1, const float* __restrict__ b1,
    float* __restrict__ xn, fp16* __restrict__ hh)
{
    if (blockIdx.x < TC_BLOCKS) {
        int id = blockIdx.x * 256 + threadIdx.x;
        const int S0 = 512 * 1536, S1 = S0 + 512 * 512, S2 = S1 + 512 * 2048;
        const float* W; fp16* T; int K, N, i;
        bool qscale = false;
        if (id < S0)      { W = Wq; T = Tq; K = 512;  N = 1536; i = id; qscale = true; }
        else if (id < S1) { W = Wo; T = To; K = 512;  N = 512;  i = id - S0; }
        else if (id < S2) { W = W1; T = T1; K = 512;  N = 2048; i = id - S1; }
        else              { W = W2; T = T2; K = 2048; N = 512;  i = id - S2; }
        int n = i / K, k = i - n * K;
        float v = W[(size_t)k * N + n];
        if (qscale && n < 512) v *= SCALE * 1.4426950408889634f;
        T[i] = __float2half_rn(v);
        return;
    }

    __shared__ float sm[32];
    size_t row = blockIdx.x - TC_BLOCKS;
    const float2* xr = (const float2*)(x + row * DIM);
    int t = threadIdx.x;

    float2 v = xr[t];
    float mu = block_sum(v.x + v.y, sm) * (1.0f / DIM);
    float d0 = v.x - mu, d1 = v.y - mu;
    float var = block_sum(d0 * d0 + d1 * d1, sm) * (1.0f / DIM);
    float r = rsqrtf(var + EPS);
    float2 w0v = ((const float2*)w0)[t];
    float2 b0v = ((const float2*)b0)[t];
    float y0 = d0 * r * w0v.x + b0v.x;
    float y1 = d1 * r * w0v.y + b0v.y;
    ((float2*)(xn + row * DIM))[t] = make_float2(y0, y1);

    float mu2 = block_sum(y0 + y1, sm) * (1.0f / DIM);
    float e0 = y0 - mu2, e1 = y1 - mu2;
    float var2 = block_sum(e0 * e0 + e1 * e1, sm) * (1.0f / DIM);
    float r2 = rsqrtf(var2 + EPS);
    float2 w1v = ((const float2*)w1)[t];
    float2 b1v = ((const float2*)b1)[t];
    *(uint32_t*)(hh + row * DIM + t * 2) =
        pack_h2(__float2half_rn(e0 * r2 * w1v.x + b1v.x),
                __float2half_rn(e1 * r2 * w1v.y + b1v.y));
}

// ---------------------------------------------------------------------------
// Launch
// ---------------------------------------------------------------------------
extern "C" void kernel_launch(void* const* d_in, const int* in_sizes, int n_in,
                              void* d_out, int out_size)
{
    (void)in_sizes; (void)n_in; (void)out_size;
    const float* x     = (const float*)d_in[0];
    const float* ln0_w = (const float*)d_in[1];
    const float* ln0_b = (const float*)d_in[2];
    const float* ln1_w = (const float*)d_in[3];
    const float* ln1_b = (const float*)d_in[4];
    const float* w_qkv = (const float*)d_in[5];
    const float* w_o   = (const float*)d_in[6];
    const float* b_o   = (const float*)d_in[7];
    const float* w1    = (const float*)d_in[8];
    const float* b1    = (const float*)d_in[9];
    const float* w2    = (const float*)d_in[10];
    const float* b2    = (const float*)d_in[11];
    float* out = (float*)d_out;

    void *p;
    cudaGetSymbolAddress(&p, g_xn);    float* xn   = (float*)p;
    cudaGetSymbolAddress(&p, g_hh);    fp16* hh    = (fp16*)p;
    cudaGetSymbolAddress(&p, g_qkvh);  fp16* qkvh  = (fp16*)p;
    cudaGetSymbolAddress(&p, g_aoh);   fp16* aoh   = (fp16*)p;
    cudaGetSymbolAddress(&p, g_x2);    float* x2   = (float*)p;
    cudaGetSymbolAddress(&p, g_x2h);   fp16* x2h   = (fp16*)p;
    cudaGetSymbolAddress(&p, g_midh);  fp16* midh  = (fp16*)p;
    cudaGetSymbolAddress(&p, g_wqkvt); fp16* wqkvt = (fp16*)p;
    cudaGetSymbolAddress(&p, g_wot);   fp16* wot   = (fp16*)p;
    cudaGetSymbolAddress(&p, g_w1t);   fp16* w1t   = (fp16*)p;
    cudaGetSymbolAddress(&p, g_w2t);   fp16* w2t   = (fp16*)p;

    cudaFuncSetAttribute(mma_gemm<1,128>, cudaFuncAttributeMaxDynamicSharedMemorySize, GSMEM128);
    cudaFuncSetAttribute(mma_gemm<2,64>,  cudaFuncAttributeMaxDynamicSharedMemorySize, GSMEM64);
    cudaFuncSetAttribute(mma_gemm<3,128>, cudaFuncAttributeMaxDynamicSharedMemorySize, GSMEM128);
    cudaFuncSetAttribute(mma_gemm<4,64>,  cudaFuncAttributeMaxDynamicSharedMemorySize, GSMEM64);
    cudaFuncSetAttribute(flash_kernel,    cudaFuncAttributeMaxDynamicSharedMemorySize, FA_SMEM);

    // 1) fused prep
    prep_kernel<<<TC_BLOCKS + ROWS, 256>>>(
        w_qkv, wqkvt, w_o, wot, w1, w1t, w2, w2t,
        x, ln0_w, ln0_b, ln1_w, ln1_b, xn, hh);
    // 2) qkv = h @ w_qkv  (BN=128)
    mma_gemm<1,128><<<dim3(QKVW / 128, ROWS / 128), 256, GSMEM128>>>(
        hh, wqkvt, ROWS, QKVW, DIM, DIM, DIM,
        nullptr, nullptr, nullptr, qkvh);
    // 3) fused attention
    flash_kernel<<<dim3(16, NZ), 128, FA_SMEM>>>(qkvh, aoh);
    // 4) x2 = ao @ w_o + b_o + xn  (BN=64, 1024 blocks)
    mma_gemm<2,64><<<dim3(DIM / 64, ROWS / 128), 256, GSMEM64>>>(
        aoh, wot, ROWS, DIM, INNER, INNER, INNER,
        b_o, xn, x2, x2h);
    // 5) mid = gelu(x2 @ w1 + b1)  (BN=128)
    mma_gemm<3,128><<<dim3(HIDDEN / 128, ROWS / 128), 256, GSMEM128>>>(
        x2h, w1t, ROWS, HIDDEN, DIM, DIM, DIM,
        b1, nullptr, nullptr, midh);
    // 6) out = mid @ w2 + b2 + x2  (BN=64, 1024 blocks)
    mma_gemm<4,64><<<dim3(DIM / 64, ROWS / 128), 256, GSMEM64>>>(
        midh, w2t, ROWS, DIM, HIDDEN, HIDDEN, HIDDEN,
        b2, x2, out, nullptr);
}

// round 17
// speedup vs baseline: 1.0178x; 1.0178x over previous
#include <cuda_runtime.h>
#include <cuda_fp16.h>
#include <cstdint>
#include <math.h>

// ---------------------------------------------------------------------------
// ViT transformer block. fp16 single-pass mma.sync (fp32 accumulate).
// Dense GEMMs: BM=128, BN=128, BK=64, 3-stage cp.async ring, 2 CTAs/SM.
// x2 kept fp16-only (residual for final GEMM read from x2h; fp32 x2 removed).
// Flash attention: 128-thread CTAs, Q resident, K/V 3-stage ring, 4 CTAs/SM.
// Prep (weight transpose/cast + LN0/LN1) fused into one launch.
// ---------------------------------------------------------------------------

#define ROWS   16384
#define DIM    512
#define INNER  512
#define QKVW   1536
#define HIDDEN 2048
#define NSEQ   1024
#define NZ     128
#define SCALE  0.125f
#define EPS    1e-5f

typedef __half fp16;

// ------------------------- device scratch ---------------------------------
__device__ __align__(256) float g_xn  [(size_t)ROWS * DIM];
__device__ __align__(256) fp16  g_hh  [(size_t)ROWS * DIM];
__device__ __align__(256) fp16  g_qkvh[(size_t)ROWS * QKVW];
__device__ __align__(256) fp16  g_aoh [(size_t)ROWS * DIM];
__device__ __align__(256) fp16  g_x2h [(size_t)ROWS * DIM];
__device__ __align__(256) fp16  g_midh[(size_t)ROWS * HIDDEN];
// transposed weights [N, K], fp16
__device__ __align__(256) fp16  g_wqkvt[(size_t)QKVW * DIM];
__device__ __align__(256) fp16  g_wot  [(size_t)DIM * INNER];
__device__ __align__(256) fp16  g_w1t  [(size_t)HIDDEN * DIM];
__device__ __align__(256) fp16  g_w2t  [(size_t)DIM * HIDDEN];

// ------------------------- PTX helpers ------------------------------------
__device__ __forceinline__ uint32_t smem_u32(const void* p) {
    uint32_t a;
    asm("{ .reg .u64 t; cvta.to.shared.u64 t, %1; cvt.u32.u64 %0, t; }"
        : "=r"(a) : "l"(p));
    return a;
}
#define CP_ASYNC_16(sa, ga) \
    asm volatile("cp.async.cg.shared.global [%0], [%1], 16;" \
                 :: "r"((uint32_t)(sa)), "l"(ga) : "memory")
#define CP_COMMIT() asm volatile("cp.async.commit_group;" ::: "memory")
#define CP_WAIT0()  asm volatile("cp.async.wait_group 0;" ::: "memory")
#define CP_WAIT1()  asm volatile("cp.async.wait_group 1;" ::: "memory")

__device__ __forceinline__ void ldsm4(uint32_t* r, uint32_t addr) {
    asm volatile("ldmatrix.sync.aligned.m8n8.x4.shared.b16 {%0,%1,%2,%3}, [%4];"
        : "=r"(r[0]), "=r"(r[1]), "=r"(r[2]), "=r"(r[3]) : "r"(addr));
}
__device__ __forceinline__ void ldsm4t(uint32_t* r, uint32_t addr) {
    asm volatile("ldmatrix.sync.aligned.m8n8.x4.trans.shared.b16 {%0,%1,%2,%3}, [%4];"
        : "=r"(r[0]), "=r"(r[1]), "=r"(r[2]), "=r"(r[3]) : "r"(addr));
}
__device__ __forceinline__ void mma_fp16(float* c, const uint32_t* a, const uint32_t* b) {
    asm volatile(
        "mma.sync.aligned.m16n8k16.row.col.f32.f16.f16.f32 "
        "{%0,%1,%2,%3}, {%4,%5,%6,%7}, {%8,%9}, {%0,%1,%2,%3};"
        : "+f"(c[0]), "+f"(c[1]), "+f"(c[2]), "+f"(c[3])
        : "r"(a[0]), "r"(a[1]), "r"(a[2]), "r"(a[3]), "r"(b[0]), "r"(b[1]));
}

__device__ __forceinline__ float gelu_f(float x) {
    return 0.5f * x * (1.0f + erff(x * 0.7071067811865475f));
}
__device__ __forceinline__ uint32_t pack_h2(fp16 a, fp16 b) {
    __half2 t = __halves2half2(a, b);
    return *(uint32_t*)&t;
}

// swizzled smem addr for a 128B-row tile (rows x 64 fp16)
__device__ __forceinline__ uint32_t sw128(uint32_t base, int row, int chunk) {
    return base + row * 128 + ((chunk ^ (row & 7)) << 4);
}

// ---------------------------------------------------------------------------
// Single-pass fp16 GEMM: C[M,N] = A[M,K] @ Bt[N,K]^T
// BM=128, BN=128, BK=64, 3-stage ring, 1 barrier/iter, 2 CTAs/SM.
// EPI: 1 hi out; 2 hi(acc+bias+resF32); 3 hi(gelu(acc+bias));
//      4 fp32(acc+bias+resF16)
// ---------------------------------------------------------------------------
#define GSTAGE 32768
#define GSMEM  (3 * GSTAGE)

template <int EPI>
__global__ void __launch_bounds__(256, 2) mma_gemm(
    const fp16* __restrict__ Ahi, const fp16* __restrict__ Bhi,
    int M, int N, int K, int lda, int ldb,
    const float* __restrict__ bias, const float* __restrict__ resF,
    const fp16* __restrict__ resH,
    float* __restrict__ Cf, fp16* __restrict__ Chi)
{
    extern __shared__ char smem[];
    uint32_t sb = smem_u32(smem);
    int tid = threadIdx.x, wid = tid >> 5, lane = tid & 31;
    int row0 = blockIdx.y * 128, col0 = blockIdx.x * 128;

    const int NC = K >> 6;

    auto load_stage = [&](int c) {
        int s = c % 3;
        uint32_t st = sb + s * GSTAGE;
        int k0 = c << 6;
        #pragma unroll
        for (int l = 0; l < 8; l++) {
            int idx = tid + l * 256;
            int mat = idx >> 10, r = (idx >> 3) & 127, ch = idx & 7;
            uint32_t dst = sw128(st + mat * 16384, r, ch);
            const fp16* src = mat == 0
                ? Ahi + (size_t)(row0 + r) * lda + k0 + ch * 8
                : Bhi + (size_t)(col0 + r) * ldb + k0 + ch * 8;
            CP_ASYNC_16(dst, src);
        }
        CP_COMMIT();
    };

    float acc[4][4][4] = {};
    int mi = lane >> 3, lr = lane & 7;
    int wm = (wid >> 2) * 64;
    int wn = (wid & 3) * 32;

    load_stage(0);
    load_stage(1);

    for (int c = 0; c < NC; c++) {
        if (c + 1 < NC) { CP_WAIT1(); }
        else            { CP_WAIT0(); }
        __syncthreads();
        if (c + 2 < NC) load_stage(c + 2);

        int s = c % 3;
        uint32_t stA = sb + s * GSTAGE;
        uint32_t stB = stA + 16384;
        #pragma unroll
        for (int ks = 0; ks < 4; ks++) {
            uint32_t ah[4][4], bh[2][4];
            #pragma unroll
            for (int t = 0; t < 4; t++) {
                int row = wm + t * 16 + ((mi & 1) << 3) + lr;
                int ch  = ks * 2 + (mi >> 1);
                ldsm4(ah[t], sw128(stA, row, ch));
            }
            #pragma unroll
            for (int p = 0; p < 2; p++) {
                int row = wn + p * 16 + ((mi >> 1) << 3) + lr;
                int ch  = ks * 2 + (mi & 1);
                ldsm4(bh[p], sw128(stB, row, ch));
            }
            #pragma unroll
            for (int tm = 0; tm < 4; tm++)
                #pragma unroll
                for (int tn = 0; tn < 4; tn++)
                    mma_fp16(acc[tm][tn], ah[tm], &bh[tn >> 1][(tn & 1) * 2]);
        }
    }

    int g = lane >> 2, tc = lane & 3;
    #pragma unroll
    for (int tm = 0; tm < 4; tm++) {
        #pragma unroll
        for (int tn = 0; tn < 4; tn++) {
            int rr = row0 + wm + tm * 16 + g;
            int cc = col0 + wn + tn * 8 + tc * 2;
            #pragma unroll
            for (int half_ = 0; half_ < 2; half_++) {
                int r_ = rr + half_ * 8;
                float v0 = acc[tm][tn][half_ * 2 + 0];
                float v1 = acc[tm][tn][half_ * 2 + 1];
                size_t off = (size_t)r_ * N + cc;
                if (EPI == 2) {
                    // x2 = acc + bias + xn(fp32); store fp16 only
                    float2 b2 = *(const float2*)(bias + cc);
                    float2 r2 = *(const float2*)(resF + off);
                    v0 += b2.x + r2.x; v1 += b2.y + r2.y;
                } else if (EPI == 3) {
                    float2 b2 = *(const float2*)(bias + cc);
                    v0 = gelu_f(v0 + b2.x); v1 = gelu_f(v1 + b2.y);
                } else if (EPI == 4) {
                    // out = acc + bias + x2h(fp16); store fp32
                    float2 b2 = *(const float2*)(bias + cc);
                    __half2 rh = *(const __half2*)(resH + off);
                    float2 r2 = __half22float2(rh);
                    v0 += b2.x + r2.x; v1 += b2.y + r2.y;
                    *(float2*)(Cf + off) = make_float2(v0, v1);
                }
                if (EPI == 1 || EPI == 2 || EPI == 3) {
                    *(uint32_t*)(Chi + off) =
                        pack_h2(__float2half_rn(v0), __float2half_rn(v1));
                }
            }
        }
    }
}

// ---------------------------------------------------------------------------
// Fused flash attention (verified-best configuration).
// 128 threads, 64 q-rows/CTA, Q resident 8KB, K/V 3-stage ring, 4 CTAs/SM.
// ---------------------------------------------------------------------------
#define FA_SMEM (8192 + 3 * 16384)

__global__ void __launch_bounds__(128, 4) flash_kernel(
    const fp16* __restrict__ qkvh, fp16* __restrict__ aoh)
{
    extern __shared__ char smem[];
    uint32_t sb = smem_u32(smem);
    int tid = threadIdx.x, wid = tid >> 5, lane = tid & 31;
    int mi = lane >> 3, lr = lane & 7;
    int g = lane >> 2, tc = lane & 3;
    int z = blockIdx.y;
    int b = z >> 6, h = (z >> 3) & 7, p = z & 7;
    int row0 = blockIdx.x * 64;
    size_t base = (size_t)((b * 8 + p)) * NSEQ * QKVW + h * 64;
    const fp16* Qh = qkvh + base;
    const fp16* Kh = qkvh + base + 512;
    const fp16* Vh = qkvh + base + 1024;

    uint32_t qoff = sb;
    uint32_t soff = sb + 8192;

    #pragma unroll
    for (int l = 0; l < 4; l++) {
        int idx = tid + l * 128;
        int r = idx >> 3, ch = idx & 7;
        CP_ASYNC_16(sw128(qoff, r, ch), Qh + (size_t)(row0 + r) * QKVW + ch * 8);
    }

    auto load_stage = [&](int c) {
        int s = c % 3;
        uint32_t st = soff + s * 16384;
        int kv0 = c << 6;
        #pragma unroll
        for (int l = 0; l < 8; l++) {
            int idx = tid + l * 128;
            int mat = idx >> 9, r = (idx >> 3) & 63, ch = idx & 7;
            const fp16* src = (mat == 0 ? Kh : Vh) + (size_t)(kv0 + r) * QKVW + ch * 8;
            CP_ASYNC_16(sw128(st + mat * 8192, r, ch), src);
        }
        CP_COMMIT();
    };

    load_stage(0);
    load_stage(1);

    float m_r[2] = {-1e30f, -1e30f};
    float l_r[2] = {0.f, 0.f};
    float O[8][4] = {};
    int qr0 = wid * 16;

    for (int c = 0; c < 16; c++) {
        if (c + 1 < 16) { CP_WAIT1(); }
        else            { CP_WAIT0(); }
        __syncthreads();
        if (c + 2 < 16) load_stage(c + 2);

        int s = c % 3;
        uint32_t kh_o = soff + s * 16384;
        uint32_t vh_o = kh_o + 8192;

        float S[8][4] = {};
        #pragma unroll
        for (int ks = 0; ks < 4; ks++) {
            uint32_t ah[4];
            {
                int row = qr0 + ((mi & 1) << 3) + lr;
                int ch  = ks * 2 + (mi >> 1);
                ldsm4(ah, sw128(qoff, row, ch));
            }
            #pragma unroll
            for (int np = 0; np < 4; np++) {
                uint32_t bh[4];
                int row = np * 16 + ((mi >> 1) << 3) + lr;
                int ch  = ks * 2 + (mi & 1);
                ldsm4(bh, sw128(kh_o, row, ch));
                mma_fp16(S[np * 2],     ah, &bh[0]);
                mma_fp16(S[np * 2 + 1], ah, &bh[2]);
            }
        }

        #pragma unroll
        for (int hf = 0; hf < 2; hf++) {
            float mx = -1e30f;
            #pragma unroll
            for (int j = 0; j < 8; j++)
                mx = fmaxf(mx, fmaxf(S[j][hf * 2], S[j][hf * 2 + 1]));
            mx = fmaxf(mx, __shfl_xor_sync(0xffffffffu, mx, 1));
            mx = fmaxf(mx, __shfl_xor_sync(0xffffffffu, mx, 2));
            float mnew = fmaxf(m_r[hf], mx);
            float alpha = exp2f(m_r[hf] - mnew);
            m_r[hf] = mnew;
            float s_ = 0.f;
            #pragma unroll
            for (int j = 0; j < 8; j++) {
                float p0 = exp2f(S[j][hf * 2]     - mnew);
                float p1 = exp2f(S[j][hf * 2 + 1] - mnew);
                S[j][hf * 2] = p0; S[j][hf * 2 + 1] = p1;
                s_ += p0 + p1;
            }
            s_ += __shfl_xor_sync(0xffffffffu, s_, 1);
            s_ += __shfl_xor_sync(0xffffffffu, s_, 2);
            l_r[hf] = l_r[hf] * alpha + s_;
            #pragma unroll
            for (int j = 0; j < 8; j++) {
                O[j][hf * 2]     *= alpha;
                O[j][hf * 2 + 1] *= alpha;
            }
        }

        uint32_t ph[4][4];
        #pragma unroll
        for (int s2 = 0; s2 < 4; s2++) {
            #pragma unroll
            for (int q4 = 0; q4 < 4; q4++) {
                int j  = s2 * 2 + (q4 >> 1);
                int k0 = (q4 & 1) * 2;
                ph[s2][q4] = pack_h2(__float2half_rn(S[j][k0]),
                                     __float2half_rn(S[j][k0 + 1]));
            }
        }

        #pragma unroll
        for (int s2 = 0; s2 < 4; s2++) {
            #pragma unroll
            for (int dp = 0; dp < 4; dp++) {
                uint32_t vhh[4];
                int row = s2 * 16 + ((mi & 1) << 3) + lr;
                int chk = dp * 2 + (mi >> 1);
                ldsm4t(vhh, sw128(vh_o, row, chk));
                mma_fp16(O[dp * 2],     ph[s2], &vhh[0]);
                mma_fp16(O[dp * 2 + 1], ph[s2], &vhh[2]);
            }
        }
    }

    float inv0 = 1.0f / l_r[0], inv1 = 1.0f / l_r[1];
    size_t obase = (size_t)(b * 8 + h) * NSEQ;
    #pragma unroll
    for (int dp = 0; dp < 8; dp++) {
        int d = dp * 8 + tc * 2;
        #pragma unroll
        for (int hf = 0; hf < 2; hf++) {
            float inv = hf ? inv1 : inv0;
            int n = row0 + qr0 + g + hf * 8;
            float v0 = O[dp][hf * 2]     * inv;
            float v1 = O[dp][hf * 2 + 1] * inv;
            size_t off = (obase + n) * DIM + p * 64 + d;
            *(uint32_t*)(aoh + off) =
                pack_h2(__float2half_rn(v0), __float2half_rn(v1));
        }
    }
}

// ---------------------------------------------------------------------------
// Fused prep: weight transpose/cast + LN0/LN1.
// ---------------------------------------------------------------------------
#define TC_BLOCKS 12288

__device__ __forceinline__ float block_sum(float v, float* sm) {
    #pragma unroll
    for (int o = 16; o > 0; o >>= 1) v += __shfl_down_sync(0xffffffffu, v, o);
    int lane = threadIdx.x & 31, wid = threadIdx.x >> 5;
    if (lane == 0) sm[wid] = v;
    __syncthreads();
    v = (threadIdx.x < 8) ? sm[threadIdx.x] : 0.0f;
    if (wid == 0) {
        #pragma unroll
        for (int o = 4; o > 0; o >>= 1) v += __shfl_down_sync(0xffffffffu, v, o);
        if (lane == 0) sm[0] = v;
    }
    __syncthreads();
    float r = sm[0];
    __syncthreads();
    return r;
}

__global__ void __launch_bounds__(256) prep_kernel(
    const float* __restrict__ Wq, fp16* __restrict__ Tq,
    const float* __restrict__ Wo, fp16* __restrict__ To,
    const float* __restrict__ W1, fp16* __restrict__ T1,
    const float* __restrict__ W2, fp16* __restrict__ T2,
    const float* __restrict__ x,
    const float* __restrict__ w0, const float* __restrict__ b0,
    const float* __restrict__ w1, const float* __restrict__ b1,
    float* __restrict__ xn, fp16* __restrict__ hh)
{
    if (blockIdx.x < TC_BLOCKS) {
        int id = blockIdx.x * 256 + threadIdx.x;
        const int S0 = 512 * 1536, S1 = S0 + 512 * 512, S2 = S1 + 512 * 2048;
        const float* W; fp16* T; int K, N, i;
        bool qscale = false;
        if (id < S0)      { W = Wq; T = Tq; K = 512;  N = 1536; i = id; qscale = true; }
        else if (id < S1) { W = Wo; T = To; K = 512;  N = 512;  i = id - S0; }
        else if (id < S2) { W = W1; T = T1; K = 512;  N = 2048; i = id - S1; }
        else              { W = W2; T = T2; K = 2048; N = 512;  i = id - S2; }
        int n = i / K, k = i - n * K;
        float v = W[(size_t)k * N + n];
        if (qscale && n < 512) v *= SCALE * 1.4426950408889634f;
        T[i] = __float2half_rn(v);
        return;
    }

    __shared__ float sm[32];
    size_t row = blockIdx.x - TC_BLOCKS;
    const float2* xr = (const float2*)(x + row * DIM);
    int t = threadIdx.x;

    float2 v = xr[t];
    float mu = block_sum(v.x + v.y, sm) * (1.0f / DIM);
    float d0 = v.x - mu, d1 = v.y - mu;
    float var = block_sum(d0 * d0 + d1 * d1, sm) * (1.0f / DIM);
    float r = rsqrtf(var + EPS);
    float2 w0v = ((const float2*)w0)[t];
    float2 b0v = ((const float2*)b0)[t];
    float y0 = d0 * r * w0v.x + b0v.x;
    float y1 = d1 * r * w0v.y + b0v.y;
    ((float2*)(xn + row * DIM))[t] = make_float2(y0, y1);

    float mu2 = block_sum(y0 + y1, sm) * (1.0f / DIM);
    float e0 = y0 - mu2, e1 = y1 - mu2;
    float var2 = block_sum(e0 * e0 + e1 * e1, sm) * (1.0f / DIM);
    float r2 = rsqrtf(var2 + EPS);
    float2 w1v = ((const float2*)w1)[t];
    float2 b1v = ((const float2*)b1)[t];
    *(uint32_t*)(hh + row * DIM + t * 2) =
        pack_h2(__float2half_rn(e0 * r2 * w1v.x + b1v.x),
                __float2half_rn(e1 * r2 * w1v.y + b1v.y));
}

// ---------------------------------------------------------------------------
// Launch
// ---------------------------------------------------------------------------
extern "C" void kernel_launch(void* const* d_in, const int* in_sizes, int n_in,
                              void* d_out, int out_size)
{
    (void)in_sizes; (void)n_in; (void)out_size;
    const float* x     = (const float*)d_in[0];
    const float* ln0_w = (const float*)d_in[1];
    const float* ln0_b = (const float*)d_in[2];
    const float* ln1_w = (const float*)d_in[3];
    const float* ln1_b = (const float*)d_in[4];
    const float* w_qkv = (const float*)d_in[5];
    const float* w_o   = (const float*)d_in[6];
    const float* b_o   = (const float*)d_in[7];
    const float* w1    = (const float*)d_in[8];
    const float* b1    = (const float*)d_in[9];
    const float* w2    = (const float*)d_in[10];
    const float* b2    = (const float*)d_in[11];
    float* out = (float*)d_out;

    void *p;
    cudaGetSymbolAddress(&p, g_xn);    float* xn   = (float*)p;
    cudaGetSymbolAddress(&p, g_hh);    fp16* hh    = (fp16*)p;
    cudaGetSymbolAddress(&p, g_qkvh);  fp16* qkvh  = (fp16*)p;
    cudaGetSymbolAddress(&p, g_aoh);   fp16* aoh   = (fp16*)p;
    cudaGetSymbolAddress(&p, g_x2h);   fp16* x2h   = (fp16*)p;
    cudaGetSymbolAddress(&p, g_midh);  fp16* midh  = (fp16*)p;
    cudaGetSymbolAddress(&p, g_wqkvt); fp16* wqkvt = (fp16*)p;
    cudaGetSymbolAddress(&p, g_wot);   fp16* wot   = (fp16*)p;
    cudaGetSymbolAddress(&p, g_w1t);   fp16* w1t   = (fp16*)p;
    cudaGetSymbolAddress(&p, g_w2t);   fp16* w2t   = (fp16*)p;

    cudaFuncSetAttribute(mma_gemm<1>, cudaFuncAttributeMaxDynamicSharedMemorySize, GSMEM);
    cudaFuncSetAttribute(mma_gemm<2>, cudaFuncAttributeMaxDynamicSharedMemorySize, GSMEM);
    cudaFuncSetAttribute(mma_gemm<3>, cudaFuncAttributeMaxDynamicSharedMemorySize, GSMEM);
    cudaFuncSetAttribute(mma_gemm<4>, cudaFuncAttributeMaxDynamicSharedMemorySize, GSMEM);
    cudaFuncSetAttribute(flash_kernel, cudaFuncAttributeMaxDynamicSharedMemorySize, FA_SMEM);

    // 1) fused prep
    prep_kernel<<<TC_BLOCKS + ROWS, 256>>>(
        w_qkv, wqkvt, w_o, wot, w1, w1t, w2, w2t,
        x, ln0_w, ln0_b, ln1_w, ln1_b, xn, hh);
    // 2) qkv = h @ w_qkv  (hi out; q pre-scaled)
    mma_gemm<1><<<dim3(QKVW / 128, ROWS / 128), 256, GSMEM>>>(
        hh, wqkvt, ROWS, QKVW, DIM, DIM, DIM,
        nullptr, nullptr, nullptr, nullptr, qkvh);
    // 3) fused attention
    flash_kernel<<<dim3(16, NZ), 128, FA_SMEM>>>(qkvh, aoh);
    // 4) x2 = ao @ w_o + b_o + xn  (fp16 out only)
    mma_gemm<2><<<dim3(DIM / 128, ROWS / 128), 256, GSMEM>>>(
        aoh, wot, ROWS, DIM, INNER, INNER, INNER,
        b_o, xn, nullptr, nullptr, x2h);
    // 5) mid = gelu(x2 @ w1 + b1)  (hi out)
    mma_gemm<3><<<dim3(HIDDEN / 128, ROWS / 128), 256, GSMEM>>>(
        x2h, w1t, ROWS, HIDDEN, DIM, DIM, DIM,
        b1, nullptr, nullptr, nullptr, midh);
    // 6) out = mid @ w2 + b2 + x2h  (fp32 out, fp16 residual)
    mma_gemm<4><<<dim3(DIM / 128, ROWS / 128), 256, GSMEM>>>(
        midh, w2t, ROWS, DIM, HIDDEN, HIDDEN, HIDDEN,
        b2, nullptr, x2h, out, nullptr);
}